// round 1
// baseline (speedup 1.0000x reference)
#include <cuda_runtime.h>
#include <math.h>
#include <float.h>

#define B  4
#define C1 64      // input channels
#define C2 256     // hidden channels
#define C3 64      // output channels
#define HP 96
#define WP 96
#define HW 9216

// ---------------- scratch (device globals; no runtime allocation) ----------------
__device__ float g_h[B*C2*HW];        // fc1 output after GELU (37.7 MB)
__device__ float g_gl1[B*C1];
__device__ float g_dyn1[B*C2*C1];     // [b][o][c]
__device__ float g_gl2[B*C2*9];
__device__ float g_outA[B*C2*9];
__device__ float g_ocp2[B*C3*9];
__device__ float g_dyn2[B*C2*9*C3];   // [b][c][k][o]

// ---------------- f32x2 helpers (Blackwell packed fp32) ----------------
__device__ __forceinline__ unsigned long long pack2(float lo, float hi) {
    unsigned long long r;
    asm("mov.b64 %0, {%1, %2};" : "=l"(r) : "f"(lo), "f"(hi));
    return r;
}
__device__ __forceinline__ void fma2(unsigned long long &d, unsigned long long a, unsigned long long b) {
    asm("fma.rn.f32x2 %0, %1, %2, %0;" : "+l"(d) : "l"(a), "l"(b));
}

// ---------------- K1: gl1[b,c] = max over H*W ----------------
__global__ void k1_gl1(const float* __restrict__ x) {
    int bc = blockIdx.x;                 // b*64 + c
    const float* p = x + (size_t)bc * HW;
    float m = -FLT_MAX;
    for (int l = threadIdx.x; l < HW; l += 256) m = fmaxf(m, p[l]);
    #pragma unroll
    for (int off = 16; off; off >>= 1) m = fmaxf(m, __shfl_xor_sync(0xffffffffu, m, off));
    __shared__ float sm[8];
    if ((threadIdx.x & 31) == 0) sm[threadIdx.x >> 5] = m;
    __syncthreads();
    if (threadIdx.x == 0) {
        float r = sm[0];
        #pragma unroll
        for (int i = 1; i < 8; i++) r = fmaxf(r, sm[i]);
        g_gl1[bc] = r;
    }
}

// ---------------- K2: fc1 dynamic weights dyn1[b,o,c] ----------------
__global__ void k2_dyn1(const float* __restrict__ w1, const float* ce, const float* gd,
                        const float* gd2, const float* __restrict__ ci) {
    int b = blockIdx.x;
    int t = threadIdx.x;                 // t = o in 0..255
    __shared__ float s1[C1];             // relu(gl*ce)*gd per c
    __shared__ float sre[C1];            // relu(gl*ce) per c
    float cev = ce[0], gdv = gd[0], gd2v = gd2[0];
    if (t < C1) {
        float r = fmaxf(g_gl1[b*C1 + t] * cev, 0.f);
        sre[t] = r;
        s1[t]  = r * gdv;
    }
    __syncthreads();
    int p = t >> 5, o2 = t & 31;
    float v = 0.f;
    #pragma unroll
    for (int g = 0; g < 8; g++) v += sre[p*8+g] * ci[o2*8+g];
    float s2 = fmaxf(v, 0.f) * gd2v;
    for (int c = 0; c < C1; c++) {
        float s = s1[c] + s2;
        float sg = 1.f / (1.f + expf(-s));
        g_dyn1[(b*C2 + t)*C1 + c] = sg * w1[t*C1 + c];
    }
}

// ---------------- K3: fc1 GEMM (K=64) + exact GELU ----------------
__global__ __launch_bounds__(256) void k3_fc1(const float* __restrict__ x) {
    __shared__ float sA[64*64];          // [o_local][c]
    __shared__ float sB[64*64];          // [c][l_local]
    int b = blockIdx.z, o0 = blockIdx.y * 64, l0 = blockIdx.x * 64;
    int t = threadIdx.x;
    for (int i = t; i < 4096; i += 256) {
        int o = i >> 6, c = i & 63;
        sA[i] = g_dyn1[(b*C2 + o0 + o)*C1 + c];
        sB[i] = x[(size_t)(b*C1 + o)*HW + l0 + c];   // here o plays role of c-row, c of l
    }
    __syncthreads();
    int ty = t >> 4, tx = t & 15;
    float acc[4][4] = {};
    for (int c = 0; c < 64; c++) {
        float a[4], bb[4];
        #pragma unroll
        for (int i = 0; i < 4; i++) a[i]  = sA[(ty + 16*i)*64 + c];
        #pragma unroll
        for (int j = 0; j < 4; j++) bb[j] = sB[c*64 + tx + 16*j];
        #pragma unroll
        for (int i = 0; i < 4; i++)
            #pragma unroll
            for (int j = 0; j < 4; j++) acc[i][j] += a[i] * bb[j];
    }
    #pragma unroll
    for (int i = 0; i < 4; i++)
        #pragma unroll
        for (int j = 0; j < 4; j++) {
            float v = acc[i][j];
            v = 0.5f * v * (1.f + erff(v * 0.70710678118654752f));
            g_h[(size_t)(b*C2 + o0 + ty + 16*i)*HW + l0 + tx + 16*j] = v;
        }
}

// ---------------- K4: gl2[b,c,k] = 3x3 adaptive max pool (32x32 bins) ----------------
__global__ void k4_gl2() {
    int c = blockIdx.x, b = blockIdx.y;
    const float* p = g_h + (size_t)(b*C2 + c)*HW;
    float lm[9];
    #pragma unroll
    for (int k = 0; k < 9; k++) lm[k] = -FLT_MAX;
    for (int l = threadIdx.x; l < HW; l += 256) {
        int y = l / 96, xx = l - y*96;
        int bin = (y >> 5)*3 + (xx >> 5);
        lm[bin] = fmaxf(lm[bin], p[l]);
    }
    __shared__ float sm[9][8];
    #pragma unroll
    for (int k = 0; k < 9; k++) {
        float m = lm[k];
        #pragma unroll
        for (int off = 16; off; off >>= 1) m = fmaxf(m, __shfl_xor_sync(0xffffffffu, m, off));
        if ((threadIdx.x & 31) == 0) sm[k][threadIdx.x >> 5] = m;
    }
    __syncthreads();
    if (threadIdx.x < 9) {
        float r = sm[threadIdx.x][0];
        #pragma unroll
        for (int i = 1; i < 8; i++) r = fmaxf(r, sm[threadIdx.x][i]);
        g_gl2[(b*C2 + c)*9 + threadIdx.x] = r;
    }
}

// ---------------- K5a: fc2 gating scalars outA[b,c,k], ocp2[b,o,k] ----------------
__global__ void k5a(const float* __restrict__ ce_w, const float* __restrict__ gd_w,
                    const float* __restrict__ gd2_w, const float* __restrict__ ci_w) {
    int b = blockIdx.x, t = threadIdx.x;         // t = c (256)
    __shared__ float sre[C2][5];
    {
        float glv[9];
        #pragma unroll
        for (int k = 0; k < 9; k++) glv[k] = g_gl2[(b*C2 + t)*9 + k];
        float rc[5];
        #pragma unroll
        for (int n = 0; n < 5; n++) {
            float v = 0.f;
            #pragma unroll
            for (int k = 0; k < 9; k++) v += glv[k] * ce_w[n*9 + k];
            rc[n] = fmaxf(v, 0.f);
            sre[t][n] = rc[n];
        }
        #pragma unroll
        for (int k = 0; k < 9; k++) {
            float v = 0.f;
            #pragma unroll
            for (int n = 0; n < 5; n++) v += rc[n] * gd_w[k*5 + n];
            g_outA[(b*C2 + t)*9 + k] = v;
        }
    }
    __syncthreads();
    if (t < C3) {
        int p = t >> 1, o2 = t & 1;
        float v[5];
        #pragma unroll
        for (int n = 0; n < 5; n++) {
            float s = 0.f;
            #pragma unroll
            for (int g = 0; g < 8; g++) s += sre[p*8+g][n] * ci_w[o2*8 + g];
            v[n] = fmaxf(s, 0.f);
        }
        #pragma unroll
        for (int k = 0; k < 9; k++) {
            float s = 0.f;
            #pragma unroll
            for (int n = 0; n < 5; n++) s += v[n] * gd2_w[k*5 + n];
            g_ocp2[(b*C3 + t)*9 + k] = s;
        }
    }
}

// ---------------- K5b: dyn2[b][c][k][o] = sigmoid(outA+ocp2) * w2 ----------------
__global__ void k5b(const float* __restrict__ w2) {
    int idx = blockIdx.x * 256 + threadIdx.x;    // layout [b][c][k][o]
    int o  = idx & 63;
    int t1 = idx >> 6;
    int k  = t1 % 9;
    int t2 = t1 / 9;
    int c  = t2 & 255;
    int b  = t2 >> 8;
    float s  = g_outA[(b*C2 + c)*9 + k] + g_ocp2[(b*C3 + o)*9 + k];
    float sg = 1.f / (1.f + expf(-s));
    g_dyn2[idx] = sg * w2[(o*C2 + c)*9 + k];
}

// ---------------- K6: fc2 3x3 dynamic conv, f32x2 inner loop ----------------
// grid (36 tiles, 4 batch); block 256 = 16x16 spatial positions; all 64 o per thread
__global__ __launch_bounds__(256, 1) void k6_fc2(float* __restrict__ out) {
    int tile = blockIdx.x;
    int b = blockIdx.y;
    int y0 = (tile / 6) * 16, x0 = (tile % 6) * 16;
    int t = threadIdx.x;
    int ly = t >> 4, lx = t & 15;
    int y = y0 + ly, x = x0 + lx;

    __shared__ float sh[8*18*18];                 // h tile with halo, [cl][ry][rx]
    __shared__ unsigned long long sw64[8*9*32];   // weights, [cl][k][o-pair]

    unsigned long long acc[32];
    #pragma unroll
    for (int i = 0; i < 32; i++) acc[i] = 0ULL;

    for (int c0 = 0; c0 < C2; c0 += 8) {
        __syncthreads();
        // stage h tile (with zero-padded halo)
        for (int i = t; i < 8*324; i += 256) {
            int cl = i / 324, rem = i - cl*324;
            int ry = rem / 18, rx = rem - ry*18;
            int gy = y0 - 1 + ry, gx = x0 - 1 + rx;
            float v = 0.f;
            if (gy >= 0 && gy < 96 && gx >= 0 && gx < 96)
                v = g_h[(size_t)(b*C2 + c0 + cl)*HW + gy*96 + gx];
            sh[i] = v;
        }
        // stage weights: contiguous [cl][k][o] block
        {
            const float4* src = (const float4*)(g_dyn2 + (size_t)(b*C2 + c0)*9*64);
            float4* dst = (float4*)sw64;
            for (int i = t; i < 8*9*16; i += 256) dst[i] = src[i];
        }
        __syncthreads();

        #pragma unroll 2
        for (int cl = 0; cl < 8; cl++) {
            unsigned long long hd[9];
            #pragma unroll
            for (int dy = 0; dy < 3; dy++)
                #pragma unroll
                for (int dx = 0; dx < 3; dx++) {
                    float v = sh[cl*324 + (ly+dy)*18 + (lx+dx)];
                    hd[dy*3+dx] = pack2(v, v);
                }
            #pragma unroll
            for (int k = 0; k < 9; k++) {
                const unsigned long long* wrow = &sw64[(cl*9 + k)*32];
                #pragma unroll
                for (int op = 0; op < 32; op++)
                    fma2(acc[op], wrow[op], hd[k]);   // 2 o's per FMA2
            }
        }
    }

    size_t obase = (size_t)b*C3*HW + (size_t)y*96 + x;
    #pragma unroll
    for (int op = 0; op < 32; op++) {
        float lo, hi;
        asm("mov.b64 {%0, %1}, %2;" : "=f"(lo), "=f"(hi) : "l"(acc[op]));
        out[obase + (size_t)(2*op)  *HW] = lo;
        out[obase + (size_t)(2*op+1)*HW] = hi;
    }
}

// ---------------- launch ----------------
extern "C" void kernel_launch(void* const* d_in, const int* in_sizes, int n_in,
                              void* d_out, int out_size) {
    const float* x     = (const float*)d_in[0];
    const float* w1    = (const float*)d_in[1];
    const float* f1ce  = (const float*)d_in[2];
    const float* f1gd  = (const float*)d_in[3];
    const float* f1gd2 = (const float*)d_in[4];
    const float* f1ci  = (const float*)d_in[5];
    const float* w2    = (const float*)d_in[6];
    const float* f2ce  = (const float*)d_in[7];
    const float* f2gd  = (const float*)d_in[8];
    const float* f2gd2 = (const float*)d_in[9];
    const float* f2ci  = (const float*)d_in[10];
    float* out = (float*)d_out;

    k1_gl1<<<B*C1, 256>>>(x);
    k2_dyn1<<<B, 256>>>(w1, f1ce, f1gd, f1gd2, f1ci);
    k3_fc1<<<dim3(HW/64, C2/64, B), 256>>>(x);
    k4_gl2<<<dim3(C2, B), 256>>>();
    k5a<<<B, 256>>>(f2ce, f2gd, f2gd2, f2ci);
    k5b<<<(B*C2*9*C3)/256, 256>>>(w2);
    k6_fc2<<<dim3(36, B), 256>>>(out);
}

// round 2
// speedup vs baseline: 1.7442x; 1.7442x over previous
#include <cuda_runtime.h>
#include <math.h>
#include <float.h>

#define B  4
#define C1 64      // input channels
#define C2 256     // hidden channels
#define C3 64      // output channels
#define HW 9216

// ---------------- scratch (device globals; no runtime allocation) ----------------
__device__ float g_h[B*C2*HW];        // fc1 output after GELU (37.7 MB)
__device__ float g_gl1[B*C1];
__device__ float g_dyn1[B*C2*C1];     // [b][o][c]
__device__ float g_gl2[B*C2*9];
__device__ float g_outA[B*C2*9];
__device__ float g_ocp2[B*C3*9];
__device__ float g_dyn2[B*C2*9*C3];   // [b][c][k][o]

// ---------------- f32x2 helpers (Blackwell packed fp32) ----------------
__device__ __forceinline__ unsigned long long pack2(float lo, float hi) {
    unsigned long long r;
    asm("mov.b64 %0, {%1, %2};" : "=l"(r) : "f"(lo), "f"(hi));
    return r;
}
__device__ __forceinline__ void fma2(unsigned long long &d, unsigned long long a, unsigned long long b) {
    asm("fma.rn.f32x2 %0, %1, %2, %0;" : "+l"(d) : "l"(a), "l"(b));
}
__device__ __forceinline__ void unpack2(float &lo, float &hi, unsigned long long v) {
    asm("mov.b64 {%0, %1}, %2;" : "=f"(lo), "=f"(hi) : "l"(v));
}

// ---------------- K1: gl1[b,c] = max over H*W ----------------
__global__ void k1_gl1(const float* __restrict__ x) {
    int bc = blockIdx.x;                 // b*64 + c
    const float* p = x + (size_t)bc * HW;
    float m = -FLT_MAX;
    for (int l = threadIdx.x; l < HW; l += 256) m = fmaxf(m, p[l]);
    #pragma unroll
    for (int off = 16; off; off >>= 1) m = fmaxf(m, __shfl_xor_sync(0xffffffffu, m, off));
    __shared__ float sm[8];
    if ((threadIdx.x & 31) == 0) sm[threadIdx.x >> 5] = m;
    __syncthreads();
    if (threadIdx.x == 0) {
        float r = sm[0];
        #pragma unroll
        for (int i = 1; i < 8; i++) r = fmaxf(r, sm[i]);
        g_gl1[bc] = r;
    }
}

// ---------------- K2: fc1 dynamic weights dyn1[b,o,c] ----------------
__global__ void k2_dyn1(const float* __restrict__ w1, const float* ce, const float* gd,
                        const float* gd2, const float* __restrict__ ci) {
    int b = blockIdx.x;
    int t = threadIdx.x;                 // t = o in 0..255
    __shared__ float s1[C1];
    __shared__ float sre[C1];
    float cev = ce[0], gdv = gd[0], gd2v = gd2[0];
    if (t < C1) {
        float r = fmaxf(g_gl1[b*C1 + t] * cev, 0.f);
        sre[t] = r;
        s1[t]  = r * gdv;
    }
    __syncthreads();
    int p = t >> 5, o2 = t & 31;
    float v = 0.f;
    #pragma unroll
    for (int g = 0; g < 8; g++) v += sre[p*8+g] * ci[o2*8+g];
    float s2 = fmaxf(v, 0.f) * gd2v;
    for (int c = 0; c < C1; c++) {
        float s = s1[c] + s2;
        float sg = 1.f / (1.f + expf(-s));
        g_dyn1[(b*C2 + t)*C1 + c] = sg * w1[t*C1 + c];
    }
}

// ---------------- K3: fc1 GEMM (K=64) + exact GELU ----------------
__global__ __launch_bounds__(256) void k3_fc1(const float* __restrict__ x) {
    __shared__ float sA[64*64];          // [o_local][c]
    __shared__ float sB[64*64];          // [c][l_local]
    int b = blockIdx.z, o0 = blockIdx.y * 64, l0 = blockIdx.x * 64;
    int t = threadIdx.x;
    for (int i = t; i < 4096; i += 256) {
        int o = i >> 6, c = i & 63;
        sA[i] = g_dyn1[(b*C2 + o0 + o)*C1 + c];
        sB[i] = x[(size_t)(b*C1 + o)*HW + l0 + c];
    }
    __syncthreads();
    int ty = t >> 4, tx = t & 15;
    float acc[4][4] = {};
    for (int c = 0; c < 64; c++) {
        float a[4], bb[4];
        #pragma unroll
        for (int i = 0; i < 4; i++) a[i]  = sA[(ty + 16*i)*64 + c];
        #pragma unroll
        for (int j = 0; j < 4; j++) bb[j] = sB[c*64 + tx + 16*j];
        #pragma unroll
        for (int i = 0; i < 4; i++)
            #pragma unroll
            for (int j = 0; j < 4; j++) acc[i][j] += a[i] * bb[j];
    }
    #pragma unroll
    for (int i = 0; i < 4; i++)
        #pragma unroll
        for (int j = 0; j < 4; j++) {
            float v = acc[i][j];
            v = 0.5f * v * (1.f + erff(v * 0.70710678118654752f));
            g_h[(size_t)(b*C2 + o0 + ty + 16*i)*HW + l0 + tx + 16*j] = v;
        }
}

// ---------------- K4: gl2[b,c,k] = 3x3 adaptive max pool (32x32 bins) ----------------
// 96 threads: one column per thread, 3 running row-band maxes, zero div/mod.
__global__ void k4_gl2() {
    int c = blockIdx.x, b = blockIdx.y;
    const float* p = g_h + (size_t)(b * C2 + c) * HW + threadIdx.x;
    #pragma unroll
    for (int band = 0; band < 3; band++) {
        const float* q = p + band * 32 * 96;
        float mm = -FLT_MAX;
        #pragma unroll 8
        for (int y = 0; y < 32; y++) mm = fmaxf(mm, q[y * 96]);
        #pragma unroll
        for (int off = 16; off; off >>= 1) mm = fmaxf(mm, __shfl_xor_sync(0xffffffffu, mm, off));
        if ((threadIdx.x & 31) == 0)
            g_gl2[(b * C2 + c) * 9 + band * 3 + (threadIdx.x >> 5)] = mm;
    }
}

// ---------------- K5a: fc2 gating scalars outA[b,c,k], ocp2[b,o,k] ----------------
__global__ void k5a(const float* __restrict__ ce_w, const float* __restrict__ gd_w,
                    const float* __restrict__ gd2_w, const float* __restrict__ ci_w) {
    int b = blockIdx.x, t = threadIdx.x;         // t = c (256)
    __shared__ float sre[C2][5];
    {
        float glv[9];
        #pragma unroll
        for (int k = 0; k < 9; k++) glv[k] = g_gl2[(b*C2 + t)*9 + k];
        float rc[5];
        #pragma unroll
        for (int n = 0; n < 5; n++) {
            float v = 0.f;
            #pragma unroll
            for (int k = 0; k < 9; k++) v += glv[k] * ce_w[n*9 + k];
            rc[n] = fmaxf(v, 0.f);
            sre[t][n] = rc[n];
        }
        #pragma unroll
        for (int k = 0; k < 9; k++) {
            float v = 0.f;
            #pragma unroll
            for (int n = 0; n < 5; n++) v += rc[n] * gd_w[k*5 + n];
            g_outA[(b*C2 + t)*9 + k] = v;
        }
    }
    __syncthreads();
    if (t < C3) {
        int p = t >> 1, o2 = t & 1;
        float v[5];
        #pragma unroll
        for (int n = 0; n < 5; n++) {
            float s = 0.f;
            #pragma unroll
            for (int g = 0; g < 8; g++) s += sre[p*8+g][n] * ci_w[o2*8 + g];
            v[n] = fmaxf(s, 0.f);
        }
        #pragma unroll
        for (int k = 0; k < 9; k++) {
            float s = 0.f;
            #pragma unroll
            for (int n = 0; n < 5; n++) s += v[n] * gd2_w[k*5 + n];
            g_ocp2[(b*C3 + t)*9 + k] = s;
        }
    }
}

// ---------------- K5b: dyn2[b][c][k][o] = sigmoid(outA+ocp2) * w2 ----------------
__global__ void k5b(const float* __restrict__ w2) {
    int idx = blockIdx.x * 256 + threadIdx.x;    // layout [b][c][k][o]
    int o  = idx & 63;
    int t1 = idx >> 6;
    int k  = t1 % 9;
    int t2 = t1 / 9;
    int c  = t2 & 255;
    int b  = t2 >> 8;
    float s  = g_outA[(b*C2 + c)*9 + k] + g_ocp2[(b*C3 + o)*9 + k];
    float sg = 1.f / (1.f + expf(-s));
    g_dyn2[idx] = sg * w2[(o*C2 + c)*9 + k];
}

// ---------------- K6: fc2 3x3 dynamic conv, f32x2, 2x2 spatial quads ----------------
// grid (36 tiles, 4 batch); block 256 = 64 spatial-quads (2x2 each) x 4 o-groups (16 o each).
// Per thread: acc[4 positions][8 o-pairs]; 4x4 register window shares taps across the quad.
__global__ __launch_bounds__(256, 1) void k6_fc2(float* __restrict__ out) {
    int tile = blockIdx.x;
    int b = blockIdx.y;
    int y0 = (tile / 6) * 16, x0 = (tile % 6) * 16;
    int t = threadIdx.x;
    int og   = t >> 6;        // o-group 0..3 (16 outputs each)
    int quad = t & 63;
    int qy = quad >> 3, qx = quad & 7;

    __shared__ float sh[8 * 324];                 // h chunk [cl][18][18] with halo
    __shared__ __align__(16) float sw[8 * 576];   // weights [cl][k][o]

    unsigned long long acc[4][8];
    #pragma unroll
    for (int s = 0; s < 4; s++)
        #pragma unroll
        for (int p = 0; p < 8; p++) acc[s][p] = 0ULL;

    // ---- stage chunk 0 directly ----
    {
        const float* hb = g_h + (size_t)(b * C2) * HW;
        #pragma unroll
        for (int j = 0; j < 11; j++) {
            int idx = t + j * 256;
            if (idx < 2592) {
                int cl = idx / 324, rem = idx - cl * 324;
                int ry = rem / 18, rx = rem - ry * 18;
                int gy = y0 - 1 + ry, gx = x0 - 1 + rx;
                float v = 0.f;
                if ((unsigned)gy < 96u && (unsigned)gx < 96u)
                    v = hb[(size_t)cl * HW + gy * 96 + gx];
                sh[idx] = v;
            }
        }
        const float4* wsrc = (const float4*)(g_dyn2 + (size_t)(b * C2) * 576);
        #pragma unroll
        for (int j = 0; j < 5; j++) {
            int idx = t + j * 256;
            if (idx < 1152) ((float4*)sw)[idx] = wsrc[idx];
        }
    }
    __syncthreads();

    for (int c0 = 0; c0 < C2; c0 += 8) {
        bool nxt = (c0 + 8) < C2;
        // prefetch next h chunk into registers (hides LDG latency behind compute)
        float hv[11];
        if (nxt) {
            const float* hb = g_h + (size_t)(b * C2 + c0 + 8) * HW;
            #pragma unroll
            for (int j = 0; j < 11; j++) {
                int idx = t + j * 256;
                float v = 0.f;
                if (idx < 2592) {
                    int cl = idx / 324, rem = idx - cl * 324;
                    int ry = rem / 18, rx = rem - ry * 18;
                    int gy = y0 - 1 + ry, gx = x0 - 1 + rx;
                    if ((unsigned)gy < 96u && (unsigned)gx < 96u)
                        v = hb[(size_t)cl * HW + gy * 96 + gx];
                }
                hv[j] = v;
            }
        }

        // ---- compute ----
        const unsigned long long* swu = (const unsigned long long*)sw;
        #pragma unroll 1
        for (int cl = 0; cl < 8; cl++) {
            // 4x4 tap window covering the 2x2 quad, duplicated into f32x2 regs
            unsigned long long win[16];
            const float* shb = sh + cl * 324 + (2 * qy) * 18 + 2 * qx;
            #pragma unroll
            for (int wy = 0; wy < 4; wy++)
                #pragma unroll
                for (int wx = 0; wx < 4; wx++) {
                    float v = shb[wy * 18 + wx];
                    win[wy * 4 + wx] = pack2(v, v);
                }
            const unsigned long long* wb = swu + cl * 288 + og * 8;  // 288 = 9*32 pairs
            #pragma unroll
            for (int k = 0; k < 9; k++) {
                const int dy = k / 3, dx = k % 3;
                unsigned long long w[8];
                #pragma unroll
                for (int p = 0; p < 8; p++) w[p] = wb[k * 32 + p];
                #pragma unroll
                for (int sy = 0; sy < 2; sy++)
                    #pragma unroll
                    for (int sx = 0; sx < 2; sx++) {
                        unsigned long long hd = win[(sy + dy) * 4 + (sx + dx)];
                        #pragma unroll
                        for (int p = 0; p < 8; p++)
                            fma2(acc[sy * 2 + sx][p], w[p], hd);
                    }
            }
        }
        __syncthreads();
        if (nxt) {
            #pragma unroll
            for (int j = 0; j < 11; j++) {
                int idx = t + j * 256;
                if (idx < 2592) sh[idx] = hv[j];
            }
            const float4* wsrc = (const float4*)(g_dyn2 + (size_t)(b * C2 + c0 + 8) * 576);
            #pragma unroll
            for (int j = 0; j < 5; j++) {
                int idx = t + j * 256;
                if (idx < 1152) ((float4*)sw)[idx] = wsrc[idx];
            }
            __syncthreads();
        }
    }

    // ---- write output ----
    #pragma unroll
    for (int sy = 0; sy < 2; sy++)
        #pragma unroll
        for (int sx = 0; sx < 2; sx++) {
            int y = y0 + 2 * qy + sy, x = x0 + 2 * qx + sx;
            size_t base = (size_t)b * C3 * HW + (size_t)y * 96 + x;
            #pragma unroll
            for (int p = 0; p < 8; p++) {
                float lo, hi;
                unpack2(lo, hi, acc[sy * 2 + sx][p]);
                int o = og * 16 + 2 * p;
                out[base + (size_t)o * HW]       = lo;
                out[base + (size_t)(o + 1) * HW] = hi;
            }
        }
}

// ---------------- launch ----------------
extern "C" void kernel_launch(void* const* d_in, const int* in_sizes, int n_in,
                              void* d_out, int out_size) {
    const float* x     = (const float*)d_in[0];
    const float* w1    = (const float*)d_in[1];
    const float* f1ce  = (const float*)d_in[2];
    const float* f1gd  = (const float*)d_in[3];
    const float* f1gd2 = (const float*)d_in[4];
    const float* f1ci  = (const float*)d_in[5];
    const float* w2    = (const float*)d_in[6];
    const float* f2ce  = (const float*)d_in[7];
    const float* f2gd  = (const float*)d_in[8];
    const float* f2gd2 = (const float*)d_in[9];
    const float* f2ci  = (const float*)d_in[10];
    float* out = (float*)d_out;

    k1_gl1<<<B*C1, 256>>>(x);
    k2_dyn1<<<B, 256>>>(w1, f1ce, f1gd, f1gd2, f1ci);
    k3_fc1<<<dim3(HW/64, C2/64, B), 256>>>(x);
    k4_gl2<<<dim3(C2, B), 96>>>();
    k5a<<<B, 256>>>(f2ce, f2gd, f2gd2, f2ci);
    k5b<<<(B*C2*9*C3)/256, 256>>>(w2);
    k6_fc2<<<dim3(36, B), 256>>>(out);
}